// round 16
// baseline (speedup 1.0000x reference)
#include <cuda_runtime.h>
#include <cstdint>

// Problem constants
#define B_   4
#define TE   512
#define TD   256
#define DE   512
#define U_   128
#define NROW_E 2048
#define NROW_D 1024
#define TT   4
#define CTX_OFF (NROW_D*DE)
#define NBLK 256          // fused grid
#define RPB  12           // virtual proj rows per block (3072 total)
#define KC   32           // W k-chunk
#define WSTR 36           // Wc padded stride (floats): 16B-aligned, conflict-spread

typedef unsigned long long ull;

// Scratch (static device globals: no allocation allowed)
__device__ float g_encT[U_ * NROW_E];   // enc projection, TRANSPOSED [u][row]
__device__ float g_dec [NROW_D * U_];   // dec projection [row][u]
__device__ unsigned g_bar = 0;          // grid barrier count (self-resetting)
__device__ unsigned g_gen = 0;          // grid barrier generation

__device__ __forceinline__ float tanh_fast(float x) {
    float y;
    asm("tanh.approx.f32 %0, %1;" : "=f"(y) : "f"(x));
    return y;
}

#define FMA_F32X2(d, a, b) \
    asm("fma.rn.f32x2 %0, %1, %2, %0;" : "+l"(d) : "l"(a), "l"(b))
#define ADD_F32X2(d, a) \
    asm("add.rn.f32x2 %0, %0, %1;" : "+l"(d) : "l"(a))

__device__ __forceinline__ ull pack2(float lo, float hi) {
    ull r;
    asm("mov.b64 %0, {%1, %2};" : "=l"(r) : "f"(lo), "f"(hi));
    return r;
}
__device__ __forceinline__ float2 unpack2(ull v) {
    float lo, hi;
    asm("mov.b64 {%0, %1}, %2;" : "=f"(lo), "=f"(hi) : "l"(v));
    return make_float2(lo, hi);
}

// Shared-memory union: phase A (proj) vs phase B (attn)
struct SmemA {                       // 43008 B
    float sX[RPB * 512];             // 24KB: 12 input rows
    float Wc[U_ * WSTR];             // 18KB: W chunk, transposed [u][k]; reused as T[u*13+r]
};
struct SmemB {                       // 29456 B (R15 attn layout, reordered for alignment)
    ulonglong2 s_c0[256][2];         // ctx partial buf A
    ulonglong2 s_c1[256][2];         // ctx partial buf B
    float s_w[TE][TT];               // softmax weights [e][t]
    float sdp2[2][U_][2];            // [half][u][t-pair]
    float sV[U_];
    float sred[TT * 16];
    float ssum[TT];
};
#define SMEM_BYTES (sizeof(SmemA) > sizeof(SmemB) ? sizeof(SmemA) : sizeof(SmemB))

__global__ __launch_bounds__(1024, 2) void fused_kernel(
    const float* __restrict__ enc, const float* __restrict__ dec,
    const float* __restrict__ W1, const float* __restrict__ b1,
    const float* __restrict__ W2, const float* __restrict__ b2,
    const float* __restrict__ Vw, float* __restrict__ out)
{
    __shared__ __align__(16) char smem[SMEM_BYTES];
    SmemA* A = (SmemA*)smem;
    SmemB* S = (SmemB*)smem;

    const int tid = threadIdx.x;
    const int blk = blockIdx.x;

    // =====================================================================
    // PHASE A: projections. Block owns virtual rows [vr0, vr0+12):
    // vr < 2048 -> enc row (W1, out g_encT), else dec row (W2, out g_dec).
    // =====================================================================
    const int vr0  = blk * RPB;
    int nEnc = 2048 - vr0;
    nEnc = nEnc < 0 ? 0 : (nEnc > RPB ? RPB : nEnc);   // rows [0,nEnc) are enc

    // stage X: 12 rows x 512 floats
    {
        float4* sXv = (float4*)A->sX;
        for (int j = tid; j < RPB * 128; j += 1024) {
            int row = j >> 7, q = j & 127;
            int vr = vr0 + row;
            const float* src = (vr < 2048) ? (enc + (size_t)vr * 512)
                                           : (dec + (size_t)(vr - 2048) * 512);
            sXv[row * 128 + q] = ((const float4*)src)[q];
        }
    }

    const int u   = tid & 127;
    const int r1  = tid >> 7;           // 0..7  (output 1: row r1)
    const bool has2 = (tid < 512);      // output 2: row r2 = 8 + r1 (r1 0..3)
    const int r2  = 8 + r1;
    const int kk4 = (tid >> 7) * 4;     // this thread's W-fill k offset (0..28)

    ull acc1 = 0ULL, acc2 = 0ULL;
    __syncthreads();                    // sX ready

    #pragma unroll 1
    for (int p = 0; p < 2; p++) {
        int rlo = p ? nEnc : 0;
        int rhi = p ? RPB  : nEnc;
        if (rlo >= rhi) continue;
        const float* W = p ? W2 : W1;
        bool a1 = (r1 >= rlo) && (r1 < rhi);
        bool a2 = has2 && (r2 >= rlo) && (r2 < rhi);

        // preload chunk 0 W regs
        float w0 = W[(size_t)(kk4 + 0) * U_ + u];
        float w1 = W[(size_t)(kk4 + 1) * U_ + u];
        float w2 = W[(size_t)(kk4 + 2) * U_ + u];
        float w3 = W[(size_t)(kk4 + 3) * U_ + u];

        #pragma unroll 1
        for (int c = 0; c < 512 / KC; c++) {
            __syncthreads();            // Wc free (prev chunk consumed)
            *(float4*)&A->Wc[u * WSTR + kk4] = make_float4(w0, w1, w2, w3);
            __syncthreads();            // Wc ready
            if (c < 512 / KC - 1) {     // prefetch next chunk during compute
                int kb = (c + 1) * KC + kk4;
                w0 = W[(size_t)(kb + 0) * U_ + u];
                w1 = W[(size_t)(kb + 1) * U_ + u];
                w2 = W[(size_t)(kb + 2) * U_ + u];
                w3 = W[(size_t)(kb + 3) * U_ + u];
            }
            if (a1 | a2) {
                const float* xb1 = &A->sX[r1 * 512 + c * KC];
                const float* xb2 = &A->sX[r2 * 512 + c * KC];
                #pragma unroll
                for (int kk = 0; kk < KC; kk += 4) {
                    ulonglong2 wq = *(const ulonglong2*)&A->Wc[u * WSTR + kk];
                    if (a1) {
                        ulonglong2 x = *(const ulonglong2*)(xb1 + kk);
                        FMA_F32X2(acc1, x.x, wq.x);
                        FMA_F32X2(acc1, x.y, wq.y);
                    }
                    if (a2) {
                        ulonglong2 x = *(const ulonglong2*)(xb2 + kk);
                        FMA_F32X2(acc2, x.x, wq.x);
                        FMA_F32X2(acc2, x.y, wq.y);
                    }
                }
            }
        }
    }

    // finalize + store. enc rows staged through smem for coalesced STG.
    {
        float2 f1 = unpack2(acc1);
        float res1 = f1.x + f1.y + ((r1 < nEnc) ? b1[u] : b2[u]);
        __syncthreads();                 // compute done: Wc reusable as T
        float* T = A->Wc;                // T[u*13 + r]
        int vr1 = vr0 + r1;
        if (vr1 < 2048) T[u * 13 + r1] = res1;
        else            g_dec[(size_t)(vr1 - 2048) * U_ + u] = res1;
        if (has2) {
            float2 f2 = unpack2(acc2);
            float res2 = f2.x + f2.y + ((r2 < nEnc) ? b1[u] : b2[u]);
            int vr2 = vr0 + r2;
            if (vr2 < 2048) T[u * 13 + r2] = res2;
            else            g_dec[(size_t)(vr2 - 2048) * U_ + u] = res2;
        }
        __syncthreads();
        for (int j = tid; j < nEnc * U_; j += 1024) {
            int u2 = j / nEnc, rr = j - u2 * nEnc;
            g_encT[(size_t)u2 * NROW_E + vr0 + rr] = T[u2 * 13 + rr];
        }
    }

    // =====================================================================
    // GRID BARRIER (all 256 blocks resident: occupancy 2, grid <= 2*SMs)
    // =====================================================================
    __threadfence();
    __syncthreads();
    if (tid == 0) {
        unsigned gen0 = *((volatile unsigned*)&g_gen);
        unsigned prev = atomicAdd(&g_bar, 1);
        if (prev == NBLK - 1) {
            g_bar = 0;                   // reset for next graph replay
            __threadfence();
            atomicAdd(&g_gen, 1);        // release
        } else {
            while (*((volatile unsigned*)&g_gen) == gen0) __nanosleep(128);
        }
    }
    __syncthreads();
    __threadfence();

    // =====================================================================
    // PHASE B: fused score + softmax + context (R15-proven body).
    // =====================================================================
    int b  = blk >> 6;                   // / (TD/TT = 64)
    int t0 = (blk & 63) * TT;
    int half = tid >> 9;                 // 0 or 1
    int eth  = tid & 511;                // e index (score phase)
    const int tb = half * 2;             // this half's t pair

    if (tid < TT * U_) {
        int t = tid >> 7, uu = tid & 127;
        S->sdp2[t >> 1][uu][t & 1] = g_dec[(size_t)(b * TD + t0) * U_ + tid];
    }
    if (tid < U_) S->sV[tid] = Vw[tid];
    __syncthreads();

    // ---- score: thread owns e = eth, t in [tb, tb+2); 4-u chunks ----
    float acc0 = 0.f, accB = 0.f;
    const float* ep = g_encT + (size_t)b * TE + eth;
#pragma unroll 2
    for (int uc = 0; uc < U_; uc += 4) {
        float4 vv4 = *(const float4*)&S->sV[uc];
        float4 dq0 = *(const float4*)&S->sdp2[half][uc][0];
        float4 dq1 = *(const float4*)&S->sdp2[half][uc + 2][0];
        float ev0 = ep[(size_t)(uc + 0) * NROW_E];
        float ev1 = ep[(size_t)(uc + 1) * NROW_E];
        float ev2 = ep[(size_t)(uc + 2) * NROW_E];
        float ev3 = ep[(size_t)(uc + 3) * NROW_E];
        acc0 += vv4.x * tanh_fast(ev0 + dq0.x);
        accB += vv4.x * tanh_fast(ev0 + dq0.y);
        acc0 += vv4.y * tanh_fast(ev1 + dq0.z);
        accB += vv4.y * tanh_fast(ev1 + dq0.w);
        acc0 += vv4.z * tanh_fast(ev2 + dq1.x);
        accB += vv4.z * tanh_fast(ev2 + dq1.y);
        acc0 += vv4.w * tanh_fast(ev3 + dq1.z);
        accB += vv4.w * tanh_fast(ev3 + dq1.w);
    }
    // (V_b dropped: softmax is shift-invariant)

    // ---- softmax (no max pass: |score| <= sum|V| ~ 10, exp safe) ----
    int lane = tid & 31, wid = tid >> 5;
    int wloc = wid & 15;
    float p0 = __expf(acc0);
    float p1 = __expf(accB);
    {
        float v0 = p0, v1 = p1;
#pragma unroll
        for (int o = 16; o; o >>= 1) {
            v0 += __shfl_xor_sync(0xffffffffu, v0, o);
            v1 += __shfl_xor_sync(0xffffffffu, v1, o);
        }
        if (lane == 0) {
            S->sred[(tb + 0) * 16 + wloc] = v0;
            S->sred[(tb + 1) * 16 + wloc] = v1;
        }
    }
    __syncthreads();
    if (wid < TT) {
        float v = (lane < 16) ? S->sred[wid * 16 + lane] : 0.f;
#pragma unroll
        for (int o = 8; o; o >>= 1)
            v += __shfl_xor_sync(0xffffffffu, v, o);
        if (lane == 0) S->ssum[wid] = v;
    }
    __syncthreads();

    {
        float w0 = p0 / S->ssum[tb + 0];
        float w1 = p1 / S->ssum[tb + 1];
        *(float2*)&S->s_w[eth][tb] = make_float2(w0, w1);
        out[CTX_OFF + (size_t)(b * TD + t0 + tb + 0) * TE + eth] = w0;
        out[CTX_OFF + (size_t)(b * TD + t0 + tb + 1) * TE + eth] = w1;
    }
    __syncthreads();

    // ---- context: thread owns d = {2*dp2, 2*dp2+1}, eg owns 128 e ----
    int dp2 = tid & 255;
    int eg  = tid >> 8;
    const float2* eb =
        (const float2*)(enc + ((size_t)b * TE + eg * 128) * DE) + dp2;

    ull a00 = 0ULL, a01 = 0ULL, a10 = 0ULL, a11 = 0ULL;
#pragma unroll 4
    for (int ei = 0; ei < 128; ei++) {
        float2 ev = __ldg(eb + (size_t)ei * (DE / 2));
        ull ev0 = pack2(ev.x, ev.x);
        ull ev1 = pack2(ev.y, ev.y);
        ulonglong2 q = *(const ulonglong2*)&S->s_w[eg * 128 + ei][0];
        FMA_F32X2(a00, q.x, ev0);
        FMA_F32X2(a01, q.y, ev0);
        FMA_F32X2(a10, q.x, ev1);
        FMA_F32X2(a11, q.y, ev1);
    }

    if (eg == 1) { S->s_c0[dp2][0] = make_ulonglong2(a00, a01);
                   S->s_c0[dp2][1] = make_ulonglong2(a10, a11); }
    if (eg == 3) { S->s_c1[dp2][0] = make_ulonglong2(a00, a01);
                   S->s_c1[dp2][1] = make_ulonglong2(a10, a11); }
    __syncthreads();
    if (eg == 0) {
        ulonglong2 x0 = S->s_c0[dp2][0], x1 = S->s_c0[dp2][1];
        ADD_F32X2(a00, x0.x); ADD_F32X2(a01, x0.y);
        ADD_F32X2(a10, x1.x); ADD_F32X2(a11, x1.y);
    }
    if (eg == 2) {
        ulonglong2 x0 = S->s_c1[dp2][0], x1 = S->s_c1[dp2][1];
        ADD_F32X2(a00, x0.x); ADD_F32X2(a01, x0.y);
        ADD_F32X2(a10, x1.x); ADD_F32X2(a11, x1.y);
    }
    __syncthreads();
    if (eg == 2) { S->s_c0[dp2][0] = make_ulonglong2(a00, a01);
                   S->s_c0[dp2][1] = make_ulonglong2(a10, a11); }
    __syncthreads();
    if (eg == 0) {
        ulonglong2 x0 = S->s_c0[dp2][0], x1 = S->s_c0[dp2][1];
        ADD_F32X2(a00, x0.x); ADD_F32X2(a01, x0.y);
        ADD_F32X2(a10, x1.x); ADD_F32X2(a11, x1.y);

        float2 c0a = unpack2(a00), c0b = unpack2(a01);
        float2 c1a = unpack2(a10), c1b = unpack2(a11);
        float c0[TT] = {c0a.x, c0a.y, c0b.x, c0b.y};
        float c1[TT] = {c1a.x, c1a.y, c1b.x, c1b.y};
#pragma unroll
        for (int t = 0; t < TT; t++)
            *(float2*)&out[(size_t)(b * TD + t0 + t) * DE + dp2 * 2] =
                make_float2(c0[t], c1[t]);
    }
}

// ---------------------------------------------------------------------------
extern "C" void kernel_launch(void* const* d_in, const int* in_sizes, int n_in,
                              void* d_out, int out_size)
{
    (void)in_sizes; (void)n_in; (void)out_size;
    const float* enc = (const float*)d_in[0];
    const float* dec = (const float*)d_in[1];
    const float* W1  = (const float*)d_in[2];
    const float* b1  = (const float*)d_in[3];
    const float* W2  = (const float*)d_in[4];
    const float* b2  = (const float*)d_in[5];
    const float* Vw  = (const float*)d_in[6];
    // d_in[7] = V_b: unused (cancels in softmax)
    float* out = (float*)d_out;

    fused_kernel<<<NBLK, 1024>>>(enc, dec, W1, b1, W2, b2, Vw, out);
}

// round 17
// speedup vs baseline: 1.5925x; 1.5925x over previous
#include <cuda_runtime.h>
#include <cstdint>

// Problem constants
#define B_   4
#define TE   512
#define TD   256
#define DE   512
#define U_   128
#define NROW_E 2048
#define NROW_D 1024
#define TT   4
#define CTX_OFF (NROW_D*DE)
#define PROWS 8          // proj rows per block

typedef unsigned long long ull;

// Scratch (static device globals: no allocation allowed)
__device__ float g_encT[U_ * NROW_E];   // enc projection, TRANSPOSED [u][row]
__device__ float g_dec [NROW_D * U_];   // dec projection [row][u]

__device__ __forceinline__ float tanh_fast(float x) {
    float y;
    asm("tanh.approx.f32 %0, %1;" : "=f"(y) : "f"(x));
    return y;
}

#define FMA_F32X2(d, a, b) \
    asm("fma.rn.f32x2 %0, %1, %2, %0;" : "+l"(d) : "l"(a), "l"(b))
#define ADD_F32X2(d, a) \
    asm("add.rn.f32x2 %0, %0, %1;" : "+l"(d) : "l"(a))

__device__ __forceinline__ ull pack2(float lo, float hi) {
    ull r;
    asm("mov.b64 %0, {%1, %2};" : "=l"(r) : "f"(lo), "f"(hi));
    return r;
}
__device__ __forceinline__ float2 unpack2(ull v) {
    float lo, hi;
    asm("mov.b64 {%0, %1}, %2;" : "=f"(lo), "=f"(hi) : "l"(v));
    return make_float2(lo, hi);
}

// ---------------------------------------------------------------------------
// Kernel 1: both input projections.
// 384 blocks x 256 threads x 8 rows (256 enc blocks + 128 dec blocks):
// 2-3 blocks/SM -> good wave balance + latency cover. Thread = (u, rg);
// owns 4 rows. k-pair-packed FFMA2 accumulators (proven R15 trick: the
// LDS.128 of sX[row][k..k+3] is already k-pair packed). Broadcast LDS
// (address is lane-invariant), coalesced W LDG (L2-resident).
// enc output staged through stride-17 smem transpose -> coalesced store.
// ---------------------------------------------------------------------------
__global__ __launch_bounds__(256) void proj_kernel(
    const float* __restrict__ enc, const float* __restrict__ dec,
    const float* __restrict__ W1, const float* __restrict__ b1,
    const float* __restrict__ W2, const float* __restrict__ b2)
{
    __shared__ __align__(16) float sX[PROWS][512];   // 16KB; reused for transpose

    const int ENC_BLOCKS = NROW_E / PROWS;   // 256
    bool isDec = (blockIdx.x >= ENC_BLOCKS);
    int blk = isDec ? (blockIdx.x - ENC_BLOCKS) : blockIdx.x;
    int rowBase = blk * PROWS;

    const float* X    = isDec ? dec : enc;
    const float* W    = isDec ? W2  : W1;
    const float* bias = isDec ? b2  : b1;

    const float4* Xv  = (const float4*)(X + (size_t)rowBase * 512);
    float4*       sXv = (float4*)&sX[0][0];
    for (int j = threadIdx.x; j < PROWS * 128; j += 256) sXv[j] = Xv[j];
    __syncthreads();

    int u  = threadIdx.x & 127;
    int rg = threadIdx.x >> 7;          // 0..1 -> rows rg*4 .. rg*4+3

    ull acc[4];
    float bv = bias[u];
#pragma unroll
    for (int i = 0; i < 4; i++) acc[i] = pack2(bv, 0.f);

    const float* Wp = W + u;
#pragma unroll 4
    for (int k = 0; k < 512; k += 4) {
        float w0 = Wp[(size_t)(k + 0) * U_];   // 4 coalesced, batched LDG
        float w1 = Wp[(size_t)(k + 1) * U_];
        float w2 = Wp[(size_t)(k + 2) * U_];
        float w3 = Wp[(size_t)(k + 3) * U_];
        ull w01 = pack2(w0, w1);
        ull w23 = pack2(w2, w3);
#pragma unroll
        for (int i = 0; i < 4; i++) {
            ulonglong2 x = *(const ulonglong2*)&sX[rg * 4 + i][k]; // bcast LDS.128
            FMA_F32X2(acc[i], x.x, w01);   // even/odd k pairs
            FMA_F32X2(acc[i], x.y, w23);
        }
    }

    float res[4];
#pragma unroll
    for (int i = 0; i < 4; i++) {
        float2 f = unpack2(acc[i]);
        res[i] = f.x + f.y;
    }

    if (isDec) {
#pragma unroll
        for (int i = 0; i < 4; i++)
            g_dec[(size_t)(rowBase + rg * 4 + i) * U_ + u] = res[i];  // coalesced
    } else {
        // stage transpose in smem (stride 17: conflict-free), store coalesced
        __syncthreads();                 // done reading sX
        float* sT = &sX[0][0];           // [u][8 rows], stride 17
#pragma unroll
        for (int i = 0; i < 4; i++)
            sT[u * 17 + rg * 4 + i] = res[i];
        __syncthreads();
        for (int j = threadIdx.x; j < 128 * PROWS; j += 256) {
            int u2 = j >> 3, r = j & 7;
            g_encT[(size_t)u2 * NROW_E + rowBase + r] = sT[u2 * 17 + r];
        }
    }
}

// ---------------------------------------------------------------------------
// Kernel 2: fused score + softmax + context for a (b, 4-t tile).
// R15-proven body; context partial-combine collapsed to ONE sync round
// (groups 1,2,3 publish to 3 buffers, group 0 absorbs all).
// ---------------------------------------------------------------------------
__global__ __launch_bounds__(1024, 2) void attn_kernel(
    const float* __restrict__ enc,
    const float* __restrict__ Vw,
    float* __restrict__ out)
{
    __shared__ __align__(16) float sdp2[2][U_][2]; // [half][u][t-pair]
    __shared__ __align__(16) float sV[U_];
    __shared__ float sred[TT * 16];
    __shared__ float ssum[TT];
    __shared__ __align__(16) float s_w[TE][TT];    // softmax weights [e][t]
    __shared__ __align__(16) ulonglong2 s_c[3][256][2];  // ctx partials (24KB)

    int b  = blockIdx.x >> 6;                // / (TD/TT = 64)
    int t0 = (blockIdx.x & 63) * TT;
    int tid  = threadIdx.x;
    int half = tid >> 9;                     // 0 or 1
    int eth  = tid & 511;                    // e index (score phase)
    const int tb = half * 2;                 // this half's t pair

    // load dec_p tile into [half][u][tl] layout, + V
    if (tid < TT * U_) {
        int t = tid >> 7, u = tid & 127;
        sdp2[t >> 1][u][t & 1] = g_dec[(size_t)(b * TD + t0) * U_ + tid];
    }
    if (tid < U_) sV[tid] = Vw[tid];
    __syncthreads();

    // ---- score phase: thread owns e = eth, t in [tb, tb+2); 4-u chunks ----
    float acc0 = 0.f, acc1 = 0.f;
    const float* ep = g_encT + (size_t)b * TE + eth;
#pragma unroll 2
    for (int uc = 0; uc < U_; uc += 4) {
        float4 vv4 = *(const float4*)&sV[uc];                 // 4 vv (1 LDS.128)
        float4 dq0 = *(const float4*)&sdp2[half][uc][0];      // u, u+1 pairs
        float4 dq1 = *(const float4*)&sdp2[half][uc + 2][0];  // u+2, u+3 pairs
        float ev0 = ep[(size_t)(uc + 0) * NROW_E];            // 4 batched LDG
        float ev1 = ep[(size_t)(uc + 1) * NROW_E];
        float ev2 = ep[(size_t)(uc + 2) * NROW_E];
        float ev3 = ep[(size_t)(uc + 3) * NROW_E];
        acc0 += vv4.x * tanh_fast(ev0 + dq0.x);
        acc1 += vv4.x * tanh_fast(ev0 + dq0.y);
        acc0 += vv4.y * tanh_fast(ev1 + dq0.z);
        acc1 += vv4.y * tanh_fast(ev1 + dq0.w);
        acc0 += vv4.z * tanh_fast(ev2 + dq1.x);
        acc1 += vv4.z * tanh_fast(ev2 + dq1.y);
        acc0 += vv4.w * tanh_fast(ev3 + dq1.z);
        acc1 += vv4.w * tanh_fast(ev3 + dq1.w);
    }
    // (V_b dropped: softmax is shift-invariant; cancels in both outputs)

    // ---- softmax over e (512 threads per half), per t; NO max pass ----
    int lane = tid & 31, wid = tid >> 5;     // 32 warps
    int wloc = wid & 15;                     // warp index within half

    float p0 = __expf(acc0);                 // |acc| <= ~10: safe in f32
    float p1 = __expf(acc1);
    {
        float v0 = p0, v1 = p1;
#pragma unroll
        for (int o = 16; o; o >>= 1) {
            v0 += __shfl_xor_sync(0xffffffffu, v0, o);
            v1 += __shfl_xor_sync(0xffffffffu, v1, o);
        }
        if (lane == 0) {
            sred[(tb + 0) * 16 + wloc] = v0;
            sred[(tb + 1) * 16 + wloc] = v1;
        }
    }
    __syncthreads();
    if (wid < TT) {
        float v = (lane < 16) ? sred[wid * 16 + lane] : 0.f;
#pragma unroll
        for (int o = 8; o; o >>= 1)
            v += __shfl_xor_sync(0xffffffffu, v, o);
        if (lane == 0) ssum[wid] = v;
    }
    __syncthreads();

    // weights -> smem [e][t] (for context) and gmem output
    {
        float w0 = p0 / ssum[tb + 0];
        float w1 = p1 / ssum[tb + 1];
        *(float2*)&s_w[eth][tb] = make_float2(w0, w1);
        out[CTX_OFF + (size_t)(b * TD + t0 + tb + 0) * TE + eth] = w0;
        out[CTX_OFF + (size_t)(b * TD + t0 + tb + 1) * TE + eth] = w1;
    }
    __syncthreads();

    // ---- context phase: thread owns d = {2*dp2, 2*dp2+1}, eg owns 128 e ----
    int dp2 = tid & 255;                 // d pair index
    int eg  = tid >> 8;                  // e-group 0..3
    const float2* eb =
        (const float2*)(enc + ((size_t)b * TE + eg * 128) * DE) + dp2;

    ull a00 = 0ULL, a01 = 0ULL, a10 = 0ULL, a11 = 0ULL;  // [d0/d1][t01/t23]
#pragma unroll 4
    for (int ei = 0; ei < 128; ei++) {
        float2 ev = __ldg(eb + (size_t)ei * (DE / 2));   // 2 d's, coalesced
        ull ev0 = pack2(ev.x, ev.x);
        ull ev1 = pack2(ev.y, ev.y);
        ulonglong2 q = *(const ulonglong2*)&s_w[eg * 128 + ei][0]; // (w0,w1),(w2,w3)
        FMA_F32X2(a00, q.x, ev0);
        FMA_F32X2(a01, q.y, ev0);
        FMA_F32X2(a10, q.x, ev1);
        FMA_F32X2(a11, q.y, ev1);
    }

    // single-round combine: groups 1,2,3 publish; group 0 absorbs all
    if (eg > 0) {
        s_c[eg - 1][dp2][0] = make_ulonglong2(a00, a01);
        s_c[eg - 1][dp2][1] = make_ulonglong2(a10, a11);
    }
    __syncthreads();
    if (eg == 0) {
#pragma unroll
        for (int g = 0; g < 3; g++) {
            ulonglong2 x0 = s_c[g][dp2][0], x1 = s_c[g][dp2][1];
            ADD_F32X2(a00, x0.x); ADD_F32X2(a01, x0.y);
            ADD_F32X2(a10, x1.x); ADD_F32X2(a11, x1.y);
        }
        float2 c0a = unpack2(a00), c0b = unpack2(a01);
        float2 c1a = unpack2(a10), c1b = unpack2(a11);
        float c0[TT] = {c0a.x, c0a.y, c0b.x, c0b.y};
        float c1[TT] = {c1a.x, c1a.y, c1b.x, c1b.y};
#pragma unroll
        for (int t = 0; t < TT; t++)
            *(float2*)&out[(size_t)(b * TD + t0 + t) * DE + dp2 * 2] =
                make_float2(c0[t], c1[t]);
    }
}

// ---------------------------------------------------------------------------
extern "C" void kernel_launch(void* const* d_in, const int* in_sizes, int n_in,
                              void* d_out, int out_size)
{
    (void)in_sizes; (void)n_in; (void)out_size;
    const float* enc = (const float*)d_in[0];
    const float* dec = (const float*)d_in[1];
    const float* W1  = (const float*)d_in[2];
    const float* b1  = (const float*)d_in[3];
    const float* W2  = (const float*)d_in[4];
    const float* b2  = (const float*)d_in[5];
    const float* Vw  = (const float*)d_in[6];
    // d_in[7] = V_b: unused (cancels in softmax)
    float* out = (float*)d_out;

    proj_kernel<<<NROW_E / PROWS + NROW_D / PROWS, 256>>>(
        enc, dec, W1, b1, W2, b2);
    attn_kernel<<<B_ * (TD / TT), 1024>>>(enc, Vw, out);
}